// round 7
// baseline (speedup 1.0000x reference)
#include <cuda_runtime.h>
#include <math_constants.h>

// Problem constants (fixed by the dataset: n=200,000 nodes, ne=12,800,000 edges)
#define MU_C   1.0f
#define DT_C   0.01f
#define EPS_C  1e-9f
#define N_MAX  262144   // >= 200,000, padded

// Device scratch (no allocations allowed in kernel_launch)
// srcP[j] = { s_j*y_j, c_j*y_j, s_j, c_j }  with s=sin(theta_j), c=cos(theta_j)
// acc[i]  = per-dst sums of srcP over incoming edges (float4 vector atomic)
__device__ float4 g_srcP[N_MAX];
__device__ float4 g_acc[N_MAX];

// ---------------------------------------------------------------------------
// Kernel 1: per-node precompute + accumulator zeroing.
// 2 nodes/thread @ TPB=128 -> grid stays 782 blocks (R4 showed grid collapse
// is the failure mode; this keeps the proven wave structure with 2x MLP).
// s = y/r, c = (x+eps)/r with r = sqrt((x+eps)^2 + y^2).
// ---------------------------------------------------------------------------
__global__ void node_init_kernel(const float* __restrict__ x,
                                 const float* __restrict__ y,
                                 int n) {
    int t = blockIdx.x * blockDim.x + threadIdx.x;
    int base = t * 2;
    const float4 zero4 = make_float4(0.f, 0.f, 0.f, 0.f);
    if (base + 1 < n) {
        float2 xv = *reinterpret_cast<const float2*>(x + base);
        float2 yv = *reinterpret_cast<const float2*>(y + base);
        {
            float xe = xv.x + EPS_C;
            float inv = rsqrtf(xe * xe + yv.x * yv.x);
            float s = yv.x * inv;
            float c = xe * inv;
            g_srcP[base] = make_float4(s * yv.x, c * yv.x, s, c);
            g_acc[base] = zero4;
        }
        {
            float xe = xv.y + EPS_C;
            float inv = rsqrtf(xe * xe + yv.y * yv.y);
            float s = yv.y * inv;
            float c = xe * inv;
            g_srcP[base + 1] = make_float4(s * yv.y, c * yv.y, s, c);
            g_acc[base + 1] = zero4;
        }
    } else if (base < n) {
        float xi = x[base], yi = y[base];
        float xe = xi + EPS_C;
        float inv = rsqrtf(xe * xe + yi * yi);
        float s = yi * inv;
        float c = xe * inv;
        g_srcP[base] = make_float4(s * yi, c * yi, s, c);
        g_acc[base] = zero4;
    }
}

// ---------------------------------------------------------------------------
// Kernel 2: edge accumulation over [e0, e1) — EXACT R5 form (twice-validated).
// For edge (j=src -> i=dst):  acc[i] += { s_j*y_j, c_j*y_j, s_j, c_j }
// 4 edges/thread, int4 index loads, gathers then vector REDs.
// ---------------------------------------------------------------------------
__global__ void edge_kernel(const int* __restrict__ edge_src,
                            const int* __restrict__ edge_dst,
                            int e0, int e1) {
    int t = blockIdx.x * blockDim.x + threadIdx.x;
    int base = e0 + t * 4;
    if (base + 3 < e1) {
        int4 si = *reinterpret_cast<const int4*>(edge_src + base);
        int4 di = *reinterpret_cast<const int4*>(edge_dst + base);
        float4 p0 = __ldg(&g_srcP[si.x]);
        float4 p1 = __ldg(&g_srcP[si.y]);
        float4 p2 = __ldg(&g_srcP[si.z]);
        float4 p3 = __ldg(&g_srcP[si.w]);
        atomicAdd(&g_acc[di.x], p0);
        atomicAdd(&g_acc[di.y], p1);
        atomicAdd(&g_acc[di.z], p2);
        atomicAdd(&g_acc[di.w], p3);
    } else if (base < e1) {
        for (int e = base; e < e1; e++) {
            float4 p = __ldg(&g_srcP[edge_src[e]]);
            atomicAdd(&g_acc[edge_dst[e]], p);
        }
    }
}

// ---------------------------------------------------------------------------
// Kernel 3: finalize, 2 nodes/thread @ TPB=128 (grid stays 782 blocks).
//   cy_i = ha_i * [ c_i*A - s_i*B - y_i*(c_i*C - s_i*D) ],  acc[i]={A,B,C,D}
//   dy   = (MU - r2)*y + w*x ; y_new = y + (dy + cy)*DT
//   angles = clip(amp*y_new + phase + b, -pi/2, pi/2)
// ---------------------------------------------------------------------------
__device__ __forceinline__ float finalize_one(float xi, float yi, float wi,
                                              float ai, float pi_, float hi,
                                              float bi, float4 a) {
    float xe = xi + EPS_C;
    float inv = rsqrtf(xe * xe + yi * yi);
    float s = yi * inv;
    float c = xe * inv;
    float cy = hi * (c * a.x - s * a.y - yi * (c * a.z - s * a.w));
    float r2 = fmaf(xi, xi, fmaf(yi, yi, EPS_C));
    float dy = (MU_C - r2) * yi + wi * xi;
    float y_new = fmaf(dy + cy, DT_C, yi);
    float ang = fmaf(ai, y_new, pi_ + bi);
    const float BOUND = 1.57079632679489661923f;  // pi/2
    return fminf(fmaxf(ang, -BOUND), BOUND);
}

__global__ void node_final_kernel(const float* __restrict__ x,
                                  const float* __restrict__ y,
                                  const float* __restrict__ w,
                                  const float* __restrict__ amp,
                                  const float* __restrict__ phase,
                                  const float* __restrict__ ha,
                                  const float* __restrict__ b,
                                  float* __restrict__ out,
                                  int n) {
    int t = blockIdx.x * blockDim.x + threadIdx.x;
    int base = t * 2;
    if (base + 1 < n) {
        float2 xv = *reinterpret_cast<const float2*>(x + base);
        float2 yv = *reinterpret_cast<const float2*>(y + base);
        float2 wv = *reinterpret_cast<const float2*>(w + base);
        float2 av = *reinterpret_cast<const float2*>(amp + base);
        float2 pv = *reinterpret_cast<const float2*>(phase + base);
        float2 hv = *reinterpret_cast<const float2*>(ha + base);
        float2 bv = *reinterpret_cast<const float2*>(b + base);
        float4 a0 = g_acc[base];
        float4 a1 = g_acc[base + 1];
        float2 o;
        o.x = finalize_one(xv.x, yv.x, wv.x, av.x, pv.x, hv.x, bv.x, a0);
        o.y = finalize_one(xv.y, yv.y, wv.y, av.y, pv.y, hv.y, bv.y, a1);
        *reinterpret_cast<float2*>(out + base) = o;
    } else if (base < n) {
        out[base] = finalize_one(x[base], y[base], w[base], amp[base],
                                 phase[base], ha[base], b[base], g_acc[base]);
    }
}

extern "C" void kernel_launch(void* const* d_in, const int* in_sizes, int n_in,
                              void* d_out, int out_size) {
    const float* x     = (const float*)d_in[0];
    const float* y     = (const float*)d_in[1];
    const float* w     = (const float*)d_in[2];
    const float* amp   = (const float*)d_in[3];
    const float* phase = (const float*)d_in[4];
    const float* ha    = (const float*)d_in[5];
    const float* b     = (const float*)d_in[6];
    const int* edge_src = (const int*)d_in[7];
    const int* edge_dst = (const int*)d_in[8];
    float* out = (float*)d_out;

    int n  = in_sizes[0];
    int ne = in_sizes[7];
    if (n > N_MAX) return;  // scratch sized for the fixed problem

    const int NODE_TPB = 128;                      // 2 nodes/thread
    int nodeThreads = (n + 1) / 2;
    int nodeBlocks = (nodeThreads + NODE_TPB - 1) / NODE_TPB;  // 782 blocks
    node_init_kernel<<<nodeBlocks, NODE_TPB>>>(x, y, n);

    // Two half-range edge launches (R2/R5-proven structure).
    const int TPB = 256;
    int half = (ne / 2) & ~3;
    {
        int thr = (half + 3) / 4;
        int blk = (thr + TPB - 1) / TPB;
        edge_kernel<<<blk, TPB>>>(edge_src, edge_dst, 0, half);
    }
    {
        int cnt = ne - half;
        int thr = (cnt + 3) / 4;
        int blk = (thr + TPB - 1) / TPB;
        edge_kernel<<<blk, TPB>>>(edge_src, edge_dst, half, ne);
    }

    node_final_kernel<<<nodeBlocks, NODE_TPB>>>(x, y, w, amp, phase, ha, b, out, n);
}

// round 8
// speedup vs baseline: 1.0601x; 1.0601x over previous
#include <cuda_runtime.h>
#include <math_constants.h>

// Problem constants (fixed by the dataset: n=200,000 nodes, ne=12,800,000 edges)
#define MU_C   1.0f
#define DT_C   0.01f
#define EPS_C  1e-9f
#define N_MAX  262144   // >= 200,000, padded

// Device scratch (no allocations allowed in kernel_launch)
// srcP[j] = { s_j*y_j, c_j*y_j, s_j, c_j }  with s=sin(theta_j), c=cos(theta_j)
// acc[i]  = per-dst sums of srcP over incoming edges (float4 vector atomic)
__device__ float4 g_srcP[N_MAX];
__device__ float4 g_acc[N_MAX];

// ---------------------------------------------------------------------------
// Kernel 1: per-node precompute + accumulator zeroing (scalar, 1 node/thread —
// fastest validated form; both vectorized variants regressed on occupancy).
// s = y/r, c = (x+eps)/r with r = sqrt((x+eps)^2 + y^2)  (== sin/cos of atan2)
// ---------------------------------------------------------------------------
__global__ void node_init_kernel(const float* __restrict__ x,
                                 const float* __restrict__ y,
                                 int n) {
    int i = blockIdx.x * blockDim.x + threadIdx.x;
    if (i >= n) return;
    float xi = x[i];
    float yi = y[i];
    float xe = xi + EPS_C;
    float inv = rsqrtf(xe * xe + yi * yi);
    float s = yi * inv;
    float c = xe * inv;
    g_srcP[i] = make_float4(s * yi, c * yi, s, c);
    g_acc[i] = make_float4(0.0f, 0.0f, 0.0f, 0.0f);
}

// ---------------------------------------------------------------------------
// Kernel 2: edge accumulation over [e0, e1). For edge (j=src -> i=dst):
//   acc[i] += { s_j*y_j, c_j*y_j, s_j, c_j }
// One float4 gather + one float4 vector RED per edge; 4 edges/thread with
// int4 index loads. Twice-validated optimum (at the diverged-lane-op floor:
// ~1 cyc gather wavefront + ~1.29 cyc spread REDG per edge per SM).
// ---------------------------------------------------------------------------
__global__ void edge_kernel(const int* __restrict__ edge_src,
                            const int* __restrict__ edge_dst,
                            int e0, int e1) {
    int t = blockIdx.x * blockDim.x + threadIdx.x;
    int base = e0 + t * 4;
    if (base + 3 < e1) {
        int4 si = *reinterpret_cast<const int4*>(edge_src + base);
        int4 di = *reinterpret_cast<const int4*>(edge_dst + base);
        float4 p0 = __ldg(&g_srcP[si.x]);
        float4 p1 = __ldg(&g_srcP[si.y]);
        float4 p2 = __ldg(&g_srcP[si.z]);
        float4 p3 = __ldg(&g_srcP[si.w]);
        atomicAdd(&g_acc[di.x], p0);
        atomicAdd(&g_acc[di.y], p1);
        atomicAdd(&g_acc[di.z], p2);
        atomicAdd(&g_acc[di.w], p3);
    } else if (base < e1) {
        for (int e = base; e < e1; e++) {
            float4 p = __ldg(&g_srcP[edge_src[e]]);
            atomicAdd(&g_acc[edge_dst[e]], p);
        }
    }
}

// ---------------------------------------------------------------------------
// Kernel 3: finalize (scalar, 1 node/thread — fastest validated form).
//   cy_i = ha_i * [ c_i*A - s_i*B - y_i*(c_i*C - s_i*D) ],  acc[i]={A,B,C,D}
//   dy   = (MU - r2)*y + w*x ; y_new = y + (dy + cy)*DT
//   angles = clip(amp*y_new + phase + b, -pi/2, pi/2)
// (dx / x_new are dead code: the output depends only on y_new.)
// ---------------------------------------------------------------------------
__global__ void node_final_kernel(const float* __restrict__ x,
                                  const float* __restrict__ y,
                                  const float* __restrict__ w,
                                  const float* __restrict__ amp,
                                  const float* __restrict__ phase,
                                  const float* __restrict__ ha,
                                  const float* __restrict__ b,
                                  float* __restrict__ out,
                                  int n) {
    int i = blockIdx.x * blockDim.x + threadIdx.x;
    if (i >= n) return;
    float xi = x[i];
    float yi = y[i];
    float xe = xi + EPS_C;
    float inv = rsqrtf(xe * xe + yi * yi);
    float s = yi * inv;
    float c = xe * inv;
    float4 a = g_acc[i];
    float cy = ha[i] * (c * a.x - s * a.y - yi * (c * a.z - s * a.w));
    float r2 = fmaf(xi, xi, fmaf(yi, yi, EPS_C));
    float dy = (MU_C - r2) * yi + w[i] * xi;
    float y_new = fmaf(dy + cy, DT_C, yi);
    float ang = fmaf(amp[i], y_new, phase[i] + b[i]);
    const float BOUND = 1.57079632679489661923f;  // pi/2
    ang = fminf(fmaxf(ang, -BOUND), BOUND);
    out[i] = ang;
}

extern "C" void kernel_launch(void* const* d_in, const int* in_sizes, int n_in,
                              void* d_out, int out_size) {
    const float* x     = (const float*)d_in[0];
    const float* y     = (const float*)d_in[1];
    const float* w     = (const float*)d_in[2];
    const float* amp   = (const float*)d_in[3];
    const float* phase = (const float*)d_in[4];
    const float* ha    = (const float*)d_in[5];
    const float* b     = (const float*)d_in[6];
    const int* edge_src = (const int*)d_in[7];
    const int* edge_dst = (const int*)d_in[8];
    float* out = (float*)d_out;

    int n  = in_sizes[0];
    int ne = in_sizes[7];
    if (n > N_MAX) return;  // scratch sized for the fixed problem

    const int TPB = 256;
    int nodeBlocks = (n + TPB - 1) / TPB;
    node_init_kernel<<<nodeBlocks, TPB>>>(x, y, n);

    // Two half-range edge launches (twice-validated structure; keeps int4
    // alignment; single-launch variant regressed).
    int half = (ne / 2) & ~3;
    {
        int cnt = half;
        int thr = (cnt + 3) / 4;
        int blk = (thr + TPB - 1) / TPB;
        edge_kernel<<<blk, TPB>>>(edge_src, edge_dst, 0, half);
    }
    {
        int cnt = ne - half;
        int thr = (cnt + 3) / 4;
        int blk = (thr + TPB - 1) / TPB;
        edge_kernel<<<blk, TPB>>>(edge_src, edge_dst, half, ne);
    }

    node_final_kernel<<<nodeBlocks, TPB>>>(x, y, w, amp, phase, ha, b, out, n);
}